// round 4
// baseline (speedup 1.0000x reference)
#include <cuda_runtime.h>
#include <cuda_bf16.h>

#define NN 50000
#define NE 600000
#define EMB 128
#define NLAYER 5
#define BN_EPS 1e-5f
#define KC 128

// ------------------------- device scratch (no allocs allowed) ---------------
__device__ float g_h[NN * 128];      // node features (input of each layer)
__device__ float g_agg[NN * 128];    // aggregated messages; reused as h2 output
__device__ float g_mid[NN * 256];    // GEMM1 output (after ReLU)
__device__ float g_comb[24 * 128];   // fused edge-embedding table e1[a0]+e2[a1]
__device__ float g_stats[256];       // [0:128) col sums, [128:256) col sumsq
__device__ int   g_deg[NN];
__device__ int   g_rowptr[NN + 1];
__device__ int   g_cursor[NN];
__device__ int   g_ssrc[NE];
__device__ int   g_scode[NE];

// ------------------------- helpers ------------------------------------------
__device__ __forceinline__ unsigned long long ffma2(unsigned long long a,
                                                    unsigned long long b,
                                                    unsigned long long c) {
    unsigned long long d;
    asm("fma.rn.f32x2 %0, %1, %2, %3;" : "=l"(d) : "l"(a), "l"(b), "l"(c));
    return d;
}
__device__ __forceinline__ unsigned long long pack2(float lo, float hi) {
    unsigned long long r;
    asm("mov.b64 %0, {%1, %2};" : "=l"(r) : "f"(lo), "f"(hi));
    return r;
}
__device__ __forceinline__ float2 unpack2(unsigned long long v) {
    float2 f;
    asm("mov.b64 {%0, %1}, %2;" : "=f"(f.x), "=f"(f.y) : "l"(v));
    return f;
}

// ------------------------- preprocessing kernels -----------------------------
__global__ void zero_deg_kernel() {
    int i = blockIdx.x * blockDim.x + threadIdx.x;
    if (i < NN) g_deg[i] = 0;
}

__global__ void hist_kernel(const int* __restrict__ dst) {
    int e = blockIdx.x * blockDim.x + threadIdx.x;
    if (e < NE) atomicAdd(&g_deg[dst[e]], 1);
}

// single-block exclusive scan over g_deg -> g_rowptr / g_cursor
__global__ void scan_kernel() {
    __shared__ int sh[1024];
    __shared__ int carry_s;
    int tid = threadIdx.x;
    if (tid == 0) carry_s = 0;
    __syncthreads();
    for (int base = 0; base < NN; base += 1024) {
        int i = base + tid;
        int v = (i < NN) ? g_deg[i] : 0;
        sh[tid] = v;
        __syncthreads();
        int carry = carry_s;
        for (int off = 1; off < 1024; off <<= 1) {
            int t = (tid >= off) ? sh[tid - off] : 0;
            __syncthreads();
            sh[tid] += t;
            __syncthreads();
        }
        int excl = carry + sh[tid] - v;
        if (i < NN) { g_rowptr[i] = excl; g_cursor[i] = excl; }
        __syncthreads();
        if (tid == 0) carry_s = carry + sh[1023];
        __syncthreads();
    }
    if (tid == 0) g_rowptr[NN] = carry_s;
}

__global__ void scatter_kernel(const int* __restrict__ src,
                               const int* __restrict__ dst,
                               const int* __restrict__ ea) {
    int e = blockIdx.x * blockDim.x + threadIdx.x;
    if (e >= NE) return;
    int d = dst[e];
    int p = atomicAdd(&g_cursor[d], 1);
    g_ssrc[p]  = src[e];
    g_scode[p] = ea[e * 2] * 4 + ea[e * 2 + 1];
}

// ------------------------- per-layer kernels ---------------------------------
__global__ void init_h_kernel(const int* __restrict__ x,
                              const float* __restrict__ atom,
                              const float* __restrict__ chir,
                              const float* __restrict__ hyb) {
    int idx = blockIdx.x * blockDim.x + threadIdx.x;   // float4 index
    if (idx >= NN * 32) return;
    int n = idx >> 5, lane = idx & 31;
    int a = x[n * 3 + 0], c = x[n * 3 + 1], hb = x[n * 3 + 2];
    float4 va = ((const float4*)atom)[a * 32 + lane];
    float4 vc = ((const float4*)chir)[c * 32 + lane];
    float4 vh = ((const float4*)hyb)[hb * 32 + lane];
    float4 o;
    o.x = va.x + vc.x + vh.x;
    o.y = va.y + vc.y + vh.y;
    o.z = va.z + vc.z + vh.z;
    o.w = va.w + vc.w + vh.w;
    ((float4*)g_h)[idx] = o;
}

// build 24-entry fused edge table for layer l, and zero stats
__global__ void comb_kernel(const float* __restrict__ e1,
                            const float* __restrict__ e2, int l) {
    int tid = threadIdx.x;
    for (int idx = tid; idx < 24 * 128; idx += 256) {
        int c = idx >> 7, k = idx & 127;
        g_comb[idx] = e1[(l * 6 + (c >> 2)) * 128 + k] +
                      e2[(l * 4 + (c & 3)) * 128 + k];
    }
    if (tid < 256) g_stats[tid] = 0.0f;
}

// one warp per node: agg[n] = sum_{e in CSR(n)} (h[src(e)] + comb[code(e)])
__global__ void aggregate_kernel() {
    int warp = (blockIdx.x * blockDim.x + threadIdx.x) >> 5;
    int lane = threadIdx.x & 31;
    if (warp >= NN) return;
    int s = g_rowptr[warp], e = g_rowptr[warp + 1];
    const float4* h4 = (const float4*)g_h;
    const float4* c4 = (const float4*)g_comb;
    float4 acc = make_float4(0.f, 0.f, 0.f, 0.f);
    #pragma unroll 2
    for (int i = s; i < e; i++) {
        int src  = g_ssrc[i];
        int code = g_scode[i];
        float4 hv = h4[src * 32 + lane];
        float4 cv = c4[code * 32 + lane];
        acc.x += hv.x + cv.x;
        acc.y += hv.y + cv.y;
        acc.z += hv.z + cv.z;
        acc.w += hv.w + cv.w;
    }
    ((float4*)g_agg)[warp * 32 + lane] = acc;
}

// GEMM: C[M,Ncols] = relu?(A[M,K] @ B[K,Ncols] + bias).
// Tile 64(M) x 128(N) per 256-thread block; K processed in chunks of KC=128.
// A staged into smem transposed AND pre-duplicated as f32x2 pairs.
// If stats != nullptr, accumulate per-column sum/sumsq of C into stats.
__global__ void __launch_bounds__(256, 1)
gemm_kernel(const float* __restrict__ A, const float* __restrict__ B,
            const float* __restrict__ bias, float* __restrict__ C,
            int M, int Ncols, int K, int relu, float* stats) {
    extern __shared__ float smem[];
    float* Bs = smem;                                           // [KC][128]
    unsigned long long* As2 = (unsigned long long*)(smem + KC * 128); // [KC][64]

    int tid = threadIdx.x;
    int m0 = blockIdx.x * 64;
    int n0 = blockIdx.y * 128;
    int w = tid >> 5, lane = tid & 31;
    int r0 = w * 8;        // 8 rows per warp
    int c0 = lane * 4;     // 4 cols per lane

    unsigned long long acc[8][2];
    #pragma unroll
    for (int i = 0; i < 8; i++) { acc[i][0] = 0ull; acc[i][1] = 0ull; }

    for (int kc = 0; kc < K; kc += KC) {
        // stage B chunk [KC x 128]
        for (int i = tid; i < KC * 32; i += 256) {
            int k = i >> 5, cs = (i & 31) * 4;
            float4 v = *(const float4*)&B[(kc + k) * Ncols + n0 + cs];
            *(float4*)&Bs[k * 128 + cs] = v;
        }
        // stage A chunk transposed + duplicated [KC][64] of f32x2
        for (int i = tid; i < 64 * (KC / 4); i += 256) {
            int r  = i & 63;
            int kk = (i >> 6) * 4;
            float4 v = make_float4(0.f, 0.f, 0.f, 0.f);
            int row = m0 + r;
            if (row < M) v = *(const float4*)&A[row * K + kc + kk];
            As2[(kk + 0) * 64 + r] = pack2(v.x, v.x);
            As2[(kk + 1) * 64 + r] = pack2(v.y, v.y);
            As2[(kk + 2) * 64 + r] = pack2(v.z, v.z);
            As2[(kk + 3) * 64 + r] = pack2(v.w, v.w);
        }
        __syncthreads();

        #pragma unroll 2
        for (int k = 0; k < KC; k++) {
            ulonglong2 b = *(const ulonglong2*)(Bs + k * 128 + c0);
            const ulonglong2* ap = (const ulonglong2*)(As2 + k * 64 + r0);
            #pragma unroll
            for (int j = 0; j < 4; j++) {
                ulonglong2 a = ap[j];
                acc[2*j  ][0] = ffma2(a.x, b.x, acc[2*j  ][0]);
                acc[2*j  ][1] = ffma2(a.x, b.y, acc[2*j  ][1]);
                acc[2*j+1][0] = ffma2(a.y, b.x, acc[2*j+1][0]);
                acc[2*j+1][1] = ffma2(a.y, b.y, acc[2*j+1][1]);
            }
        }
        __syncthreads();
    }

    // epilogue: bias (+relu), store, optional column stats
    float4 bv = *(const float4*)&bias[n0 + c0];
    float lsum[4] = {0.f, 0.f, 0.f, 0.f};
    float lsq[4]  = {0.f, 0.f, 0.f, 0.f};
    #pragma unroll
    for (int i = 0; i < 8; i++) {
        int row = m0 + r0 + i;
        if (row < M) {
            float2 v0 = unpack2(acc[i][0]);
            float2 v1 = unpack2(acc[i][1]);
            float o0 = v0.x + bv.x, o1 = v0.y + bv.y;
            float o2 = v1.x + bv.z, o3 = v1.y + bv.w;
            if (relu) {
                o0 = fmaxf(o0, 0.f); o1 = fmaxf(o1, 0.f);
                o2 = fmaxf(o2, 0.f); o3 = fmaxf(o3, 0.f);
            }
            *(float4*)&C[row * Ncols + n0 + c0] = make_float4(o0, o1, o2, o3);
            if (stats) {
                lsum[0] += o0; lsum[1] += o1; lsum[2] += o2; lsum[3] += o3;
                lsq[0] += o0 * o0; lsq[1] += o1 * o1;
                lsq[2] += o2 * o2; lsq[3] += o3 * o3;
            }
        }
    }
    if (stats) {
        __syncthreads();   // smem is free now; reuse for reduction
        float* sred  = smem;          // [8][128]
        float* sqred = smem + 1024;   // [8][128]
        #pragma unroll
        for (int j = 0; j < 4; j++) {
            sred [w * 128 + c0 + j] = lsum[j];
            sqred[w * 128 + c0 + j] = lsq[j];
        }
        __syncthreads();
        if (tid < 128) {
            float s = 0.f, q = 0.f;
            #pragma unroll
            for (int ww = 0; ww < 8; ww++) {
                s += sred [ww * 128 + tid];
                q += sqred[ww * 128 + tid];
            }
            atomicAdd(&stats[tid], s);
            atomicAdd(&stats[128 + tid], q);
        }
    }
}

// BatchNorm (+optional ReLU): out = gamma*(x-mu)*rsqrt(var+eps)+beta
__global__ void bn_kernel(const float* __restrict__ h2,
                          const float* __restrict__ gamma,
                          const float* __restrict__ beta,
                          float* __restrict__ out, int relu) {
    __shared__ float sc[128], sh[128];
    int tid = threadIdx.x;
    if (tid < 128) {
        float mu  = g_stats[tid] * (1.0f / NN);
        float var = g_stats[128 + tid] * (1.0f / NN) - mu * mu;
        float s = gamma[tid] * rsqrtf(var + BN_EPS);
        sc[tid] = s;
        sh[tid] = beta[tid] - mu * s;
    }
    __syncthreads();
    int idx = blockIdx.x * blockDim.x + tid;   // float4 index
    if (idx >= NN * 32) return;
    int c = (idx & 31) * 4;
    float4 v = ((const float4*)h2)[idx];
    float4 o;
    o.x = v.x * sc[c + 0] + sh[c + 0];
    o.y = v.y * sc[c + 1] + sh[c + 1];
    o.z = v.z * sc[c + 2] + sh[c + 2];
    o.w = v.w * sc[c + 3] + sh[c + 3];
    if (relu) {
        o.x = fmaxf(o.x, 0.f); o.y = fmaxf(o.y, 0.f);
        o.z = fmaxf(o.z, 0.f); o.w = fmaxf(o.w, 0.f);
    }
    ((float4*)out)[idx] = o;
}

// ------------------------- host launcher -------------------------------------
extern "C" void kernel_launch(void* const* d_in, const int* in_sizes, int n_in,
                              void* d_out, int out_size) {
    const int*   x          = (const int*)d_in[0];
    const int*   edge_index = (const int*)d_in[1];
    const int*   edge_attr  = (const int*)d_in[2];
    const float* atom       = (const float*)d_in[3];
    const float* chir       = (const float*)d_in[4];
    const float* hyb        = (const float*)d_in[5];
    const float* e1         = (const float*)d_in[6];
    const float* e2         = (const float*)d_in[7];
    const float* W1         = (const float*)d_in[8];
    const float* b1         = (const float*)d_in[9];
    const float* W2         = (const float*)d_in[10];
    const float* b2         = (const float*)d_in[11];
    const float* gamma      = (const float*)d_in[12];
    const float* beta       = (const float*)d_in[13];
    float* out = (float*)d_out;

    const int* src = edge_index;
    const int* dst = edge_index + NE;

    float *p_h, *p_agg, *p_mid, *p_stats;
    cudaGetSymbolAddress((void**)&p_h, g_h);
    cudaGetSymbolAddress((void**)&p_agg, g_agg);
    cudaGetSymbolAddress((void**)&p_mid, g_mid);
    cudaGetSymbolAddress((void**)&p_stats, g_stats);

    const int smem_gemm = KC * 128 * 4 + KC * 64 * 8;   // 128 KB
    cudaFuncSetAttribute(gemm_kernel,
                         cudaFuncAttributeMaxDynamicSharedMemorySize, smem_gemm);

    // preprocessing: CSR-sort edges by destination (same result every call)
    zero_deg_kernel<<<(NN + 255) / 256, 256>>>();
    hist_kernel<<<(NE + 255) / 256, 256>>>(dst);
    scan_kernel<<<1, 1024>>>();
    scatter_kernel<<<(NE + 255) / 256, 256>>>(src, dst, edge_attr);

    // input node embedding
    init_h_kernel<<<(NN * 32 + 255) / 256, 256>>>(x, atom, chir, hyb);

    const int mblocks = (NN + 63) / 64;   // 782
    for (int l = 0; l < NLAYER; l++) {
        comb_kernel<<<1, 256>>>(e1, e2, l);
        aggregate_kernel<<<(NN * 32 + 255) / 256, 256>>>();
        // GEMM1: agg[N,128] @ W1[l][128,256] + b1 -> relu -> mid
        gemm_kernel<<<dim3(mblocks, 2), 256, smem_gemm>>>(
            p_agg, W1 + (size_t)l * 128 * 256, b1 + l * 256, p_mid,
            NN, 256, 128, 1, nullptr);
        // GEMM2: mid[N,256] @ W2[l][256,128] + b2 -> h2 (into g_agg), + stats
        gemm_kernel<<<dim3(mblocks, 1), 256, smem_gemm>>>(
            p_mid, W2 + (size_t)l * 256 * 128, b2 + l * 128, p_agg,
            NN, 128, 256, 0, p_stats);
        // BN (+ relu except last layer); last layer writes d_out
        float* dest = (l == NLAYER - 1) ? out : p_h;
        bn_kernel<<<(NN * 32 + 255) / 256, 256>>>(
            p_agg, gamma + l * 128, beta + l * 128, dest, l == NLAYER - 1 ? 0 : 1);
    }
}

// round 7
// speedup vs baseline: 2.1481x; 2.1481x over previous
#include <cuda_runtime.h>
#include <cuda_bf16.h>
#include <cstdint>

#define NN 50000
#define NE 600000
#define NLAYER 5
#define BN_EPS 1e-5f

// ------------------------- device scratch (no allocs allowed) ---------------
__device__ float g_h[NN * 128];                 // node features (fp32)
__device__ float g_h2[NN * 128];                // GEMM2 output (pre-BN, fp32)
__device__ __nv_bfloat16 g_aggh[NN * 128];      // aggregated msgs, bf16 hi
__device__ __nv_bfloat16 g_aggl[NN * 128];      // aggregated msgs, bf16 lo
__device__ __nv_bfloat16 g_midh[NN * 256];      // GEMM1 output, bf16 hi
__device__ __nv_bfloat16 g_midl[NN * 256];      // GEMM1 output, bf16 lo
__device__ __nv_bfloat16 g_w1th[NLAYER * 256 * 128];  // W1^T split hi
__device__ __nv_bfloat16 g_w1tl[NLAYER * 256 * 128];  // W1^T split lo
__device__ __nv_bfloat16 g_w2th[NLAYER * 128 * 256];  // W2^T split hi
__device__ __nv_bfloat16 g_w2tl[NLAYER * 128 * 256];  // W2^T split lo
__device__ float g_comb[24 * 128];              // fused edge-emb table
__device__ float g_stats[256];                  // col sums / sumsq
__device__ int   g_deg[NN];
__device__ int   g_rowptr[NN + 1];
__device__ int   g_cursor[NN];
__device__ int   g_ssrc[NE];
__device__ int   g_scode[NE];

// ------------------------- helpers ------------------------------------------
__device__ __forceinline__ uint32_t split_pack(float a, float b, uint32_t& lo) {
    __nv_bfloat16 ha = __float2bfloat16_rn(a), hb = __float2bfloat16_rn(b);
    float ra = a - __bfloat162float(ha), rb = b - __bfloat162float(hb);
    __nv_bfloat16 la = __float2bfloat16_rn(ra), lb = __float2bfloat16_rn(rb);
    lo = (uint32_t)__bfloat16_as_ushort(la) | ((uint32_t)__bfloat16_as_ushort(lb) << 16);
    return (uint32_t)__bfloat16_as_ushort(ha) | ((uint32_t)__bfloat16_as_ushort(hb) << 16);
}

__device__ __forceinline__ void mma_bf16(float* d, uint32_t a0, uint32_t a1,
                                         uint32_t a2, uint32_t a3,
                                         uint32_t b0, uint32_t b1) {
    asm volatile(
        "mma.sync.aligned.m16n8k16.row.col.f32.bf16.bf16.f32 "
        "{%0,%1,%2,%3}, {%4,%5,%6,%7}, {%8,%9}, {%0,%1,%2,%3};"
        : "+f"(d[0]), "+f"(d[1]), "+f"(d[2]), "+f"(d[3])
        : "r"(a0), "r"(a1), "r"(a2), "r"(a3), "r"(b0), "r"(b1));
}

// ------------------------- preprocessing -------------------------------------
__global__ void zero_deg_kernel() {
    int i = blockIdx.x * blockDim.x + threadIdx.x;
    if (i < NN) g_deg[i] = 0;
}
__global__ void hist_kernel(const int* __restrict__ dst) {
    int e = blockIdx.x * blockDim.x + threadIdx.x;
    if (e < NE) atomicAdd(&g_deg[dst[e]], 1);
}
__global__ void scan_kernel() {
    __shared__ int sh[1024];
    __shared__ int carry_s;
    int tid = threadIdx.x;
    if (tid == 0) carry_s = 0;
    __syncthreads();
    for (int base = 0; base < NN; base += 1024) {
        int i = base + tid;
        int v = (i < NN) ? g_deg[i] : 0;
        sh[tid] = v;
        __syncthreads();
        int carry = carry_s;
        for (int off = 1; off < 1024; off <<= 1) {
            int t = (tid >= off) ? sh[tid - off] : 0;
            __syncthreads();
            sh[tid] += t;
            __syncthreads();
        }
        int excl = carry + sh[tid] - v;
        if (i < NN) { g_rowptr[i] = excl; g_cursor[i] = excl; }
        __syncthreads();
        if (tid == 0) carry_s = carry + sh[1023];
        __syncthreads();
    }
    if (tid == 0) g_rowptr[NN] = carry_s;
}
__global__ void scatter_kernel(const int* __restrict__ src,
                               const int* __restrict__ dst,
                               const int* __restrict__ ea) {
    int e = blockIdx.x * blockDim.x + threadIdx.x;
    if (e >= NE) return;
    int d = dst[e];
    int p = atomicAdd(&g_cursor[d], 1);
    g_ssrc[p]  = src[e];
    g_scode[p] = ea[e * 2] * 4 + ea[e * 2 + 1];
}

// ------------------------- per-layer kernels ---------------------------------
__global__ void init_h_kernel(const int* __restrict__ x,
                              const float* __restrict__ atom,
                              const float* __restrict__ chir,
                              const float* __restrict__ hyb) {
    int idx = blockIdx.x * blockDim.x + threadIdx.x;
    if (idx >= NN * 32) return;
    int n = idx >> 5, lane = idx & 31;
    int a = x[n * 3 + 0], c = x[n * 3 + 1], hb = x[n * 3 + 2];
    float4 va = ((const float4*)atom)[a * 32 + lane];
    float4 vc = ((const float4*)chir)[c * 32 + lane];
    float4 vh = ((const float4*)hyb)[hb * 32 + lane];
    float4 o;
    o.x = va.x + vc.x + vh.x;
    o.y = va.y + vc.y + vh.y;
    o.z = va.z + vc.z + vh.z;
    o.w = va.w + vc.w + vh.w;
    ((float4*)g_h)[idx] = o;
}

// transpose + bf16-split all layers' weights (once per launch)
__global__ void wconv_kernel(const float* __restrict__ W1,
                             const float* __restrict__ W2) {
    int i = blockIdx.x * blockDim.x + threadIdx.x;
    if (i >= NLAYER * 256 * 128) return;
    {   // W1T[l][n(256)][k(128)]
        int l = i / 32768, r = i % 32768, n = r >> 7, k = r & 127;
        float v = W1[(l * 128 + k) * 256 + n];
        __nv_bfloat16 h = __float2bfloat16_rn(v);
        g_w1th[i] = h;
        g_w1tl[i] = __float2bfloat16_rn(v - __bfloat162float(h));
    }
    {   // W2T[l][n(128)][k(256)]
        int l = i / 32768, r = i % 32768, n = r >> 8, k = r & 255;
        float v = W2[(l * 256 + k) * 128 + n];
        __nv_bfloat16 h = __float2bfloat16_rn(v);
        g_w2th[i] = h;
        g_w2tl[i] = __float2bfloat16_rn(v - __bfloat162float(h));
    }
}

__global__ void comb_kernel(const float* __restrict__ e1,
                            const float* __restrict__ e2, int l) {
    int tid = threadIdx.x;
    for (int idx = tid; idx < 24 * 128; idx += 256) {
        int c = idx >> 7, k = idx & 127;
        g_comb[idx] = e1[(l * 6 + (c >> 2)) * 128 + k] +
                      e2[(l * 4 + (c & 3)) * 128 + k];
    }
    if (tid < 256) g_stats[tid] = 0.0f;
}

// one warp per node; emits bf16 hi/lo split of the fp32 aggregate
__global__ void aggregate_kernel() {
    int warp = (blockIdx.x * blockDim.x + threadIdx.x) >> 5;
    int lane = threadIdx.x & 31;
    if (warp >= NN) return;
    int s = g_rowptr[warp], e = g_rowptr[warp + 1];
    const float4* h4 = (const float4*)g_h;
    const float4* c4 = (const float4*)g_comb;
    float4 acc = make_float4(0.f, 0.f, 0.f, 0.f);
    #pragma unroll 2
    for (int i = s; i < e; i++) {
        int src  = g_ssrc[i];
        int code = g_scode[i];
        float4 hv = h4[src * 32 + lane];
        float4 cv = c4[code * 32 + lane];
        acc.x += hv.x + cv.x;
        acc.y += hv.y + cv.y;
        acc.z += hv.z + cv.z;
        acc.w += hv.w + cv.w;
    }
    uint2 hv, lv;
    hv.x = split_pack(acc.x, acc.y, lv.x);
    hv.y = split_pack(acc.z, acc.w, lv.y);
    ((uint2*)g_aggh)[warp * 32 + lane] = hv;
    ((uint2*)g_aggl)[warp * 32 + lane] = lv;
}

// ------------------------- split-bf16 HMMA GEMM ------------------------------
// C_tile[128,128] = A[128,K] @ B^T  (B given as [N][K], i.e. transposed).
// A, B are (hi, lo) bf16 splits; 3 mma passes: Ah*Bh + Ah*Bl + Al*Bh, fp32 acc.
// Block: 256 threads = 8 warps (4 along M x 2 along N); warp tile 32x64.
// K staged in chunks of 64; smem row pitch 36 words (conflict-free frags).
// mode 1: out = relu(C + bias) -> bf16 hi/lo (row stride Nout)
// mode 2: out = C + bias       -> fp32       (row stride 128)
#define PITCH 36
#define TILE_WORDS (128 * PITCH)             // per hi/lo array, uint32 words
#define SMEM_MMA (4 * TILE_WORDS * 4)        // 73728 bytes

__global__ void __launch_bounds__(256)
mma_gemm_kernel(const __nv_bfloat16* __restrict__ Ah,
                const __nv_bfloat16* __restrict__ Al,
                const __nv_bfloat16* __restrict__ Bh,
                const __nv_bfloat16* __restrict__ Bl,
                const float* __restrict__ bias,
                int M, int K, int Nout, int mode,
                __nv_bfloat16* __restrict__ outh,
                __nv_bfloat16* __restrict__ outl,
                float* __restrict__ outf) {
    extern __shared__ uint32_t smem[];
    uint32_t* sAh = smem;
    uint32_t* sAl = smem + TILE_WORDS;
    uint32_t* sBh = smem + 2 * TILE_WORDS;
    uint32_t* sBl = smem + 3 * TILE_WORDS;

    const int tid  = threadIdx.x;
    const int lane = tid & 31;
    const int wid  = tid >> 5;
    const int wm   = wid & 3;          // 0..3 -> M offset wm*32
    const int wn   = wid >> 2;         // 0..1 -> N offset wn*64
    const int g    = lane >> 2;        // 0..7
    const int tq   = lane & 3;         // 0..3
    const int m0 = blockIdx.x * 128;
    const int n0 = blockIdx.y * 128;

    float acc[2][8][4];
    #pragma unroll
    for (int mt = 0; mt < 2; mt++)
        #pragma unroll
        for (int nt = 0; nt < 8; nt++)
            #pragma unroll
            for (int j = 0; j < 4; j++) acc[mt][nt][j] = 0.f;

    for (int kc = 0; kc < K; kc += 64) {
        // ---- stage: 128 rows x 64 bf16 per array; uint4 = 8 bf16 = 4 words
        for (int idx = tid; idx < 1024; idx += 256) {
            int row = idx >> 3, c8 = idx & 7;
            uint4 za = make_uint4(0, 0, 0, 0), zb = za, a_h = za, a_l = za;
            int m = m0 + row;
            if (m < M) {
                size_t ab = (size_t)m * K + kc + c8 * 8;
                a_h = *(const uint4*)(Ah + ab);
                a_l = *(const uint4*)(Al + ab);
            }
            size_t bb = (size_t)(n0 + row) * K + kc + c8 * 8;
            uint4 b_h = *(const uint4*)(Bh + bb);
            uint4 b_l = *(const uint4*)(Bl + bb);
            int so = row * PITCH + c8 * 4;
            *(uint4*)(sAh + so) = a_h;
            *(uint4*)(sAl + so) = a_l;
            *(uint4*)(sBh + so) = b_h;
            *(uint4*)(sBl + so) = b_l;
            (void)za; (void)zb;
        }
        __syncthreads();

        // ---- compute: 4 k16-steps per chunk
        #pragma unroll
        for (int kw = 0; kw < 4; kw++) {
            const int ko = kw * 8 + tq;
            uint32_t bhf[8][2], blf[8][2];
            #pragma unroll
            for (int nt = 0; nt < 8; nt++) {
                int bo = (wn * 64 + nt * 8 + g) * PITCH + ko;
                bhf[nt][0] = sBh[bo];     bhf[nt][1] = sBh[bo + 4];
                blf[nt][0] = sBl[bo];     blf[nt][1] = sBl[bo + 4];
            }
            #pragma unroll
            for (int mt = 0; mt < 2; mt++) {
                int ao = (wm * 32 + mt * 16 + g) * PITCH + ko;
                uint32_t ah0 = sAh[ao];              uint32_t ah1 = sAh[ao + 8 * PITCH];
                uint32_t ah2 = sAh[ao + 4];          uint32_t ah3 = sAh[ao + 8 * PITCH + 4];
                uint32_t al0 = sAl[ao];              uint32_t al1 = sAl[ao + 8 * PITCH];
                uint32_t al2 = sAl[ao + 4];          uint32_t al3 = sAl[ao + 8 * PITCH + 4];
                #pragma unroll
                for (int nt = 0; nt < 8; nt++) {
                    mma_bf16(acc[mt][nt], ah0, ah1, ah2, ah3, bhf[nt][0], bhf[nt][1]);
                    mma_bf16(acc[mt][nt], ah0, ah1, ah2, ah3, blf[nt][0], blf[nt][1]);
                    mma_bf16(acc[mt][nt], al0, al1, al2, al3, bhf[nt][0], bhf[nt][1]);
                }
            }
        }
        __syncthreads();
    }

    // ---- epilogue
    #pragma unroll
    for (int nt = 0; nt < 8; nt++) {
        int col = n0 + wn * 64 + nt * 8 + 2 * tq;
        float bv0 = bias[col], bv1 = bias[col + 1];
        #pragma unroll
        for (int mt = 0; mt < 2; mt++) {
            int r0 = m0 + wm * 32 + mt * 16 + g;
            float* d = acc[mt][nt];
            if (mode == 1) {
                if (r0 < M) {
                    float a = fmaxf(d[0] + bv0, 0.f), b = fmaxf(d[1] + bv1, 0.f);
                    uint32_t lo, hi = split_pack(a, b, lo);
                    size_t o = (size_t)r0 * Nout + col;
                    *(uint32_t*)(outh + o) = hi;
                    *(uint32_t*)(outl + o) = lo;
                }
                if (r0 + 8 < M) {
                    float a = fmaxf(d[2] + bv0, 0.f), b = fmaxf(d[3] + bv1, 0.f);
                    uint32_t lo, hi = split_pack(a, b, lo);
                    size_t o = (size_t)(r0 + 8) * Nout + col;
                    *(uint32_t*)(outh + o) = hi;
                    *(uint32_t*)(outl + o) = lo;
                }
            } else {
                if (r0 < M)
                    *(float2*)(outf + (size_t)r0 * 128 + col) =
                        make_float2(d[0] + bv0, d[1] + bv1);
                if (r0 + 8 < M)
                    *(float2*)(outf + (size_t)(r0 + 8) * 128 + col) =
                        make_float2(d[2] + bv0, d[3] + bv1);
            }
        }
    }
}

// ------------------------- BN stats + transform ------------------------------
__global__ void stats_kernel(const float* __restrict__ h2) {
    __shared__ float sred[1024], sqred[1024];
    int tid = threadIdx.x, w = tid >> 5, lane = tid & 31;
    int gw = blockIdx.x * 8 + w;
    int stride = gridDim.x * 8;
    float4 s = make_float4(0.f, 0.f, 0.f, 0.f);
    float4 q = make_float4(0.f, 0.f, 0.f, 0.f);
    for (int r = gw; r < NN; r += stride) {
        float4 v = ((const float4*)h2)[r * 32 + lane];
        s.x += v.x; s.y += v.y; s.z += v.z; s.w += v.w;
        q.x += v.x * v.x; q.y += v.y * v.y;
        q.z += v.z * v.z; q.w += v.w * v.w;
    }
    sred [w * 128 + lane * 4 + 0] = s.x;  sred [w * 128 + lane * 4 + 1] = s.y;
    sred [w * 128 + lane * 4 + 2] = s.z;  sred [w * 128 + lane * 4 + 3] = s.w;
    sqred[w * 128 + lane * 4 + 0] = q.x;  sqred[w * 128 + lane * 4 + 1] = q.y;
    sqred[w * 128 + lane * 4 + 2] = q.z;  sqred[w * 128 + lane * 4 + 3] = q.w;
    __syncthreads();
    if (tid < 128) {
        float a = 0.f, b = 0.f;
        #pragma unroll
        for (int ww = 0; ww < 8; ww++) {
            a += sred [ww * 128 + tid];
            b += sqred[ww * 128 + tid];
        }
        atomicAdd(&g_stats[tid], a);
        atomicAdd(&g_stats[128 + tid], b);
    }
}

__global__ void bn_kernel(const float* __restrict__ h2,
                          const float* __restrict__ gamma,
                          const float* __restrict__ beta,
                          float* __restrict__ out, int relu) {
    __shared__ float sc[128], sh[128];
    int tid = threadIdx.x;
    if (tid < 128) {
        float mu  = g_stats[tid] * (1.0f / NN);
        float var = g_stats[128 + tid] * (1.0f / NN) - mu * mu;
        float s = gamma[tid] * rsqrtf(var + BN_EPS);
        sc[tid] = s;
        sh[tid] = beta[tid] - mu * s;
    }
    __syncthreads();
    int idx = blockIdx.x * blockDim.x + tid;
    if (idx >= NN * 32) return;
    int c = (idx & 31) * 4;
    float4 v = ((const float4*)h2)[idx];
    float4 o;
    o.x = v.x * sc[c + 0] + sh[c + 0];
    o.y = v.y * sc[c + 1] + sh[c + 1];
    o.z = v.z * sc[c + 2] + sh[c + 2];
    o.w = v.w * sc[c + 3] + sh[c + 3];
    if (relu) {
        o.x = fmaxf(o.x, 0.f); o.y = fmaxf(o.y, 0.f);
        o.z = fmaxf(o.z, 0.f); o.w = fmaxf(o.w, 0.f);
    }
    ((float4*)out)[idx] = o;
}

// ------------------------- host launcher -------------------------------------
extern "C" void kernel_launch(void* const* d_in, const int* in_sizes, int n_in,
                              void* d_out, int out_size) {
    const int*   x          = (const int*)d_in[0];
    const int*   edge_index = (const int*)d_in[1];
    const int*   edge_attr  = (const int*)d_in[2];
    const float* atom       = (const float*)d_in[3];
    const float* chir       = (const float*)d_in[4];
    const float* hyb        = (const float*)d_in[5];
    const float* e1         = (const float*)d_in[6];
    const float* e2         = (const float*)d_in[7];
    const float* W1         = (const float*)d_in[8];
    const float* b1         = (const float*)d_in[9];
    const float* W2         = (const float*)d_in[10];
    const float* b2         = (const float*)d_in[11];
    const float* gamma      = (const float*)d_in[12];
    const float* beta       = (const float*)d_in[13];
    float* out = (float*)d_out;

    const int* src = edge_index;
    const int* dst = edge_index + NE;

    float *p_h, *p_h2;
    __nv_bfloat16 *p_aggh, *p_aggl, *p_midh, *p_midl;
    __nv_bfloat16 *p_w1th, *p_w1tl, *p_w2th, *p_w2tl;
    cudaGetSymbolAddress((void**)&p_h, g_h);
    cudaGetSymbolAddress((void**)&p_h2, g_h2);
    cudaGetSymbolAddress((void**)&p_aggh, g_aggh);
    cudaGetSymbolAddress((void**)&p_aggl, g_aggl);
    cudaGetSymbolAddress((void**)&p_midh, g_midh);
    cudaGetSymbolAddress((void**)&p_midl, g_midl);
    cudaGetSymbolAddress((void**)&p_w1th, g_w1th);
    cudaGetSymbolAddress((void**)&p_w1tl, g_w1tl);
    cudaGetSymbolAddress((void**)&p_w2th, g_w2th);
    cudaGetSymbolAddress((void**)&p_w2tl, g_w2tl);

    cudaFuncSetAttribute(mma_gemm_kernel,
                         cudaFuncAttributeMaxDynamicSharedMemorySize, SMEM_MMA);

    // preprocessing: CSR-sort edges by destination
    zero_deg_kernel<<<(NN + 255) / 256, 256>>>();
    hist_kernel<<<(NE + 255) / 256, 256>>>(dst);
    scan_kernel<<<1, 1024>>>();
    scatter_kernel<<<(NE + 255) / 256, 256>>>(src, dst, edge_attr);

    init_h_kernel<<<(NN * 32 + 255) / 256, 256>>>(x, atom, chir, hyb);
    wconv_kernel<<<(NLAYER * 256 * 128 + 255) / 256, 256>>>(W1, W2);

    const int mb = (NN + 127) / 128;   // 391
    for (int l = 0; l < NLAYER; l++) {
        comb_kernel<<<1, 256>>>(e1, e2, l);
        aggregate_kernel<<<(NN * 32 + 255) / 256, 256>>>();
        // GEMM1: agg[N,128] @ W1^T -> relu -> mid (bf16 split), 2 N-tiles
        mma_gemm_kernel<<<dim3(mb, 2), 256, SMEM_MMA>>>(
            p_aggh, p_aggl,
            p_w1th + (size_t)l * 256 * 128, p_w1tl + (size_t)l * 256 * 128,
            b1 + l * 256, NN, 128, 256, 1, p_midh, p_midl, nullptr);
        // GEMM2: mid[N,256] @ W2^T -> h2 (fp32)
        mma_gemm_kernel<<<dim3(mb, 1), 256, SMEM_MMA>>>(
            p_midh, p_midl,
            p_w2th + (size_t)l * 128 * 256, p_w2tl + (size_t)l * 128 * 256,
            b2 + l * 128, NN, 256, 128, 2, nullptr, nullptr, p_h2);
        stats_kernel<<<256, 256>>>(p_h2);
        float* dest = (l == NLAYER - 1) ? out : p_h;
        bn_kernel<<<(NN * 32 + 255) / 256, 256>>>(
            p_h2, gamma + l * 128, beta + l * 128, dest,
            l == NLAYER - 1 ? 0 : 1);
    }
}

// round 11
// speedup vs baseline: 2.3019x; 1.0716x over previous
#include <cuda_runtime.h>
#include <cuda_bf16.h>
#include <cstdint>

#define NN 50000
#define NE 600000
#define NLAYER 5
#define BN_EPS 1e-5f
#define NBLK_SCAN 49   // ceil(NN/1024)

// ------------------------- device scratch (no allocs allowed) ---------------
__device__ float g_h[NN * 128];                 // layer-0 node features (fp32)
__device__ float g_h2[NN * 128];                // GEMM2 output (pre-BN, fp32)
__device__ __nv_bfloat16 g_aggh[NN * 128];      // aggregated msgs, bf16 hi
__device__ __nv_bfloat16 g_aggl[NN * 128];      // aggregated msgs, bf16 lo
__device__ __nv_bfloat16 g_midh[NN * 256];      // GEMM1 output, bf16 hi
__device__ __nv_bfloat16 g_midl[NN * 256];      // GEMM1 output, bf16 lo
__device__ __nv_bfloat16 g_w1th[NLAYER * 256 * 128];  // W1^T split hi
__device__ __nv_bfloat16 g_w1tl[NLAYER * 256 * 128];  // W1^T split lo
__device__ __nv_bfloat16 g_w2th[NLAYER * 128 * 256];  // W2^T split hi
__device__ __nv_bfloat16 g_w2tl[NLAYER * 128 * 256];  // W2^T split lo
__device__ float g_comb[24 * 128];              // fused edge-emb table
__device__ float g_scsh[256];                   // [0:128) scale, [128:256) shift
__device__ float g_stats[256];                  // col sums / sumsq
__device__ int   g_deg[NN];
__device__ int   g_rowptr[NN + 1];
__device__ int   g_cursor[NN];
__device__ int   g_blksum[NBLK_SCAN];
__device__ int   g_blkoff[NBLK_SCAN];
__device__ int   g_ssrc[NE];
__device__ int   g_scode[NE];

// ------------------------- helpers ------------------------------------------
__device__ __forceinline__ uint32_t split_pack(float a, float b, uint32_t& lo) {
    __nv_bfloat16 ha = __float2bfloat16_rn(a), hb = __float2bfloat16_rn(b);
    float ra = a - __bfloat162float(ha), rb = b - __bfloat162float(hb);
    __nv_bfloat16 la = __float2bfloat16_rn(ra), lb = __float2bfloat16_rn(rb);
    lo = (uint32_t)__bfloat16_as_ushort(la) | ((uint32_t)__bfloat16_as_ushort(lb) << 16);
    return (uint32_t)__bfloat16_as_ushort(ha) | ((uint32_t)__bfloat16_as_ushort(hb) << 16);
}

__device__ __forceinline__ void mma_bf16(float* d, uint32_t a0, uint32_t a1,
                                         uint32_t a2, uint32_t a3,
                                         uint32_t b0, uint32_t b1) {
    asm volatile(
        "mma.sync.aligned.m16n8k16.row.col.f32.bf16.bf16.f32 "
        "{%0,%1,%2,%3}, {%4,%5,%6,%7}, {%8,%9}, {%0,%1,%2,%3};"
        : "+f"(d[0]), "+f"(d[1]), "+f"(d[2]), "+f"(d[3])
        : "r"(a0), "r"(a1), "r"(a2), "r"(a3), "r"(b0), "r"(b1));
}

// ------------------------- preprocessing -------------------------------------
__global__ void zero_deg_kernel() {
    int i = blockIdx.x * blockDim.x + threadIdx.x;
    if (i < NN) g_deg[i] = 0;
}
__global__ void hist_kernel(const int* __restrict__ dst) {
    int e = blockIdx.x * blockDim.x + threadIdx.x;
    if (e < NE) atomicAdd(&g_deg[dst[e]], 1);
}
// phase A: per-block (1024-wide) exclusive scan + block totals
__global__ void scanA_kernel() {
    __shared__ int sh[1024];
    int tid = threadIdx.x;
    int i = blockIdx.x * 1024 + tid;
    int v = (i < NN) ? g_deg[i] : 0;
    sh[tid] = v;
    __syncthreads();
    for (int off = 1; off < 1024; off <<= 1) {
        int t = (tid >= off) ? sh[tid - off] : 0;
        __syncthreads();
        sh[tid] += t;
        __syncthreads();
    }
    if (i < NN) g_rowptr[i] = sh[tid] - v;          // local exclusive
    if (tid == 1023) g_blksum[blockIdx.x] = sh[1023];
}
// phase B: scan the 49 block totals (single small block)
__global__ void scanB_kernel() {
    __shared__ int sh[64];
    int tid = threadIdx.x;
    int v = (tid < NBLK_SCAN) ? g_blksum[tid] : 0;
    sh[tid] = v;
    __syncthreads();
    for (int off = 1; off < 64; off <<= 1) {
        int t = (tid >= off) ? sh[tid - off] : 0;
        __syncthreads();
        sh[tid] += t;
        __syncthreads();
    }
    if (tid < NBLK_SCAN) g_blkoff[tid] = sh[tid] - v;
}
// phase C: add block offsets, init cursor
__global__ void scanC_kernel() {
    int i = blockIdx.x * blockDim.x + threadIdx.x;
    if (i < NN) {
        int r = g_rowptr[i] + g_blkoff[i >> 10];
        g_rowptr[i] = r;
        g_cursor[i] = r;
    }
    if (i == 0) g_rowptr[NN] = NE;
}
__global__ void scatter_kernel(const int* __restrict__ src,
                               const int* __restrict__ dst,
                               const int* __restrict__ ea) {
    int e = blockIdx.x * blockDim.x + threadIdx.x;
    if (e >= NE) return;
    int d = dst[e];
    int p = atomicAdd(&g_cursor[d], 1);
    g_ssrc[p]  = src[e];
    g_scode[p] = ea[e * 2] * 4 + ea[e * 2 + 1];
}

// ------------------------- per-layer kernels ---------------------------------
__global__ void init_h_kernel(const int* __restrict__ x,
                              const float* __restrict__ atom,
                              const float* __restrict__ chir,
                              const float* __restrict__ hyb) {
    int idx = blockIdx.x * blockDim.x + threadIdx.x;
    if (idx >= NN * 32) return;
    int n = idx >> 5, lane = idx & 31;
    int a = x[n * 3 + 0], c = x[n * 3 + 1], hb = x[n * 3 + 2];
    float4 va = ((const float4*)atom)[a * 32 + lane];
    float4 vc = ((const float4*)chir)[c * 32 + lane];
    float4 vh = ((const float4*)hyb)[hb * 32 + lane];
    float4 o;
    o.x = va.x + vc.x + vh.x;
    o.y = va.y + vc.y + vh.y;
    o.z = va.z + vc.z + vh.z;
    o.w = va.w + vc.w + vh.w;
    ((float4*)g_h)[idx] = o;
}

// transpose + bf16-split all layers' weights (once per launch)
__global__ void wconv_kernel(const float* __restrict__ W1,
                             const float* __restrict__ W2) {
    int i = blockIdx.x * blockDim.x + threadIdx.x;
    if (i >= NLAYER * 256 * 128) return;
    {   // W1T[l][n(256)][k(128)]
        int l = i / 32768, r = i % 32768, n = r >> 7, k = r & 127;
        float v = W1[(l * 128 + k) * 256 + n];
        __nv_bfloat16 h = __float2bfloat16_rn(v);
        g_w1th[i] = h;
        g_w1tl[i] = __float2bfloat16_rn(v - __bfloat162float(h));
    }
    {   // W2T[l][n(128)][k(256)]
        int l = i / 32768, r = i % 32768, n = r >> 8, k = r & 255;
        float v = W2[(l * 256 + k) * 128 + n];
        __nv_bfloat16 h = __float2bfloat16_rn(v);
        g_w2th[i] = h;
        g_w2tl[i] = __float2bfloat16_rn(v - __bfloat162float(h));
    }
}

// edge table for layer l + BN affine (scale/shift) from PREVIOUS layer's stats
__global__ void comb_kernel(const float* __restrict__ e1,
                            const float* __restrict__ e2,
                            const float* __restrict__ gamma_prev,
                            const float* __restrict__ beta_prev, int l) {
    int tid = threadIdx.x;
    for (int idx = tid; idx < 24 * 128; idx += 256) {
        int c = idx >> 7, k = idx & 127;
        g_comb[idx] = e1[(l * 6 + (c >> 2)) * 128 + k] +
                      e2[(l * 4 + (c & 3)) * 128 + k];
    }
    if (l > 0 && tid < 128) {
        float mu  = g_stats[tid] * (1.0f / NN);
        float var = g_stats[128 + tid] * (1.0f / NN) - mu * mu;
        float s = gamma_prev[tid] * rsqrtf(var + BN_EPS);
        g_scsh[tid] = s;
        g_scsh[128 + tid] = beta_prev[tid] - mu * s;
    }
}

// one warp per node; optionally applies BN(prev)+ReLU to gathered features.
// emits bf16 hi/lo split of the fp32 aggregate.
__global__ void aggregate_kernel(const float* __restrict__ hsrc, int apply_bn) {
    __shared__ float s_sc[128], s_sh[128];
    int tid = threadIdx.x;
    if (apply_bn) {
        if (tid < 128) s_sc[tid] = g_scsh[tid];
        else if (tid < 256) s_sh[tid - 128] = g_scsh[tid];
    }
    __syncthreads();
    int warp = blockIdx.x * 8 + (tid >> 5);
    int lane = tid & 31;
    if (warp >= NN) return;
    int s = g_rowptr[warp], e = g_rowptr[warp + 1];
    const float4* h4 = (const float4*)hsrc;
    const float4* c4 = (const float4*)g_comb;
    float4 sc4 = make_float4(1.f, 1.f, 1.f, 1.f);
    float4 sh4 = make_float4(0.f, 0.f, 0.f, 0.f);
    if (apply_bn) {
        sc4 = *(float4*)&s_sc[lane * 4];
        sh4 = *(float4*)&s_sh[lane * 4];
    }
    float4 acc = make_float4(0.f, 0.f, 0.f, 0.f);
    if (apply_bn) {
        #pragma unroll 2
        for (int i = s; i < e; i++) {
            int src  = g_ssrc[i];
            int code = g_scode[i];
            float4 hv = h4[src * 32 + lane];
            float4 cv = c4[code * 32 + lane];
            acc.x += fmaxf(hv.x * sc4.x + sh4.x, 0.f) + cv.x;
            acc.y += fmaxf(hv.y * sc4.y + sh4.y, 0.f) + cv.y;
            acc.z += fmaxf(hv.z * sc4.z + sh4.z, 0.f) + cv.z;
            acc.w += fmaxf(hv.w * sc4.w + sh4.w, 0.f) + cv.w;
        }
    } else {
        #pragma unroll 2
        for (int i = s; i < e; i++) {
            int src  = g_ssrc[i];
            int code = g_scode[i];
            float4 hv = h4[src * 32 + lane];
            float4 cv = c4[code * 32 + lane];
            acc.x += hv.x + cv.x;
            acc.y += hv.y + cv.y;
            acc.z += hv.z + cv.z;
            acc.w += hv.w + cv.w;
        }
    }
    uint2 hv, lv;
    hv.x = split_pack(acc.x, acc.y, lv.x);
    hv.y = split_pack(acc.z, acc.w, lv.y);
    ((uint2*)g_aggh)[warp * 32 + lane] = hv;
    ((uint2*)g_aggl)[warp * 32 + lane] = lv;
}

// ------------------------- split-bf16 HMMA GEMM ------------------------------
// C_tile[128,128] = A[128,K] @ B^T  (B given as [N][K]).
// A, B are (hi, lo) bf16 splits; 3 mma passes: Ah*Bh + Ah*Bl + Al*Bh, fp32 acc.
// Block: 256 threads = 8 warps (4M x 2N); warp tile 32x64; K chunks of 64.
// mode 1: out = relu(C + bias) -> bf16 hi/lo (row stride Nout); block(0,0)
//         zeroes g_stats (consumed-by-now, rewritten by the following mode-2).
// mode 2: out = C + bias -> fp32 (row stride 128); epilogue accumulates
//         per-column sum/sumsq into g_stats.
#define PITCH 36
#define TILE_WORDS (128 * PITCH)
#define SMEM_MMA (4 * TILE_WORDS * 4)        // 73728 bytes

__global__ void __launch_bounds__(256)
mma_gemm_kernel(const __nv_bfloat16* __restrict__ Ah,
                const __nv_bfloat16* __restrict__ Al,
                const __nv_bfloat16* __restrict__ Bh,
                const __nv_bfloat16* __restrict__ Bl,
                const float* __restrict__ bias,
                int M, int K, int Nout, int mode,
                __nv_bfloat16* __restrict__ outh,
                __nv_bfloat16* __restrict__ outl,
                float* __restrict__ outf) {
    extern __shared__ uint32_t smem[];
    uint32_t* sAh = smem;
    uint32_t* sAl = smem + TILE_WORDS;
    uint32_t* sBh = smem + 2 * TILE_WORDS;
    uint32_t* sBl = smem + 3 * TILE_WORDS;

    const int tid  = threadIdx.x;
    const int lane = tid & 31;
    const int wid  = tid >> 5;
    const int wm   = wid & 3;
    const int wn   = wid >> 2;
    const int g    = lane >> 2;
    const int tq   = lane & 3;
    const int m0 = blockIdx.x * 128;
    const int n0 = blockIdx.y * 128;

    if (mode == 1 && blockIdx.x == 0 && blockIdx.y == 0 && tid < 256)
        g_stats[tid] = 0.f;   // safe: stats consumed before this launch

    float acc[2][8][4];
    #pragma unroll
    for (int mt = 0; mt < 2; mt++)
        #pragma unroll
        for (int nt = 0; nt < 8; nt++)
            #pragma unroll
            for (int j = 0; j < 4; j++) acc[mt][nt][j] = 0.f;

    for (int kc = 0; kc < K; kc += 64) {
        for (int idx = tid; idx < 1024; idx += 256) {
            int row = idx >> 3, c8 = idx & 7;
            uint4 a_h = make_uint4(0, 0, 0, 0), a_l = a_h;
            int m = m0 + row;
            if (m < M) {
                size_t ab = (size_t)m * K + kc + c8 * 8;
                a_h = *(const uint4*)(Ah + ab);
                a_l = *(const uint4*)(Al + ab);
            }
            size_t bb = (size_t)(n0 + row) * K + kc + c8 * 8;
            uint4 b_h = *(const uint4*)(Bh + bb);
            uint4 b_l = *(const uint4*)(Bl + bb);
            int so = row * PITCH + c8 * 4;
            *(uint4*)(sAh + so) = a_h;
            *(uint4*)(sAl + so) = a_l;
            *(uint4*)(sBh + so) = b_h;
            *(uint4*)(sBl + so) = b_l;
        }
        __syncthreads();

        #pragma unroll
        for (int kw = 0; kw < 4; kw++) {
            const int ko = kw * 8 + tq;
            uint32_t bhf[8][2], blf[8][2];
            #pragma unroll
            for (int nt = 0; nt < 8; nt++) {
                int bo = (wn * 64 + nt * 8 + g) * PITCH + ko;
                bhf[nt][0] = sBh[bo];     bhf[nt][1] = sBh[bo + 4];
                blf[nt][0] = sBl[bo];     blf[nt][1] = sBl[bo + 4];
            }
            #pragma unroll
            for (int mt = 0; mt < 2; mt++) {
                int ao = (wm * 32 + mt * 16 + g) * PITCH + ko;
                uint32_t ah0 = sAh[ao];      uint32_t ah1 = sAh[ao + 8 * PITCH];
                uint32_t ah2 = sAh[ao + 4];  uint32_t ah3 = sAh[ao + 8 * PITCH + 4];
                uint32_t al0 = sAl[ao];      uint32_t al1 = sAl[ao + 8 * PITCH];
                uint32_t al2 = sAl[ao + 4];  uint32_t al3 = sAl[ao + 8 * PITCH + 4];
                #pragma unroll
                for (int nt = 0; nt < 8; nt++) {
                    mma_bf16(acc[mt][nt], ah0, ah1, ah2, ah3, bhf[nt][0], bhf[nt][1]);
                    mma_bf16(acc[mt][nt], ah0, ah1, ah2, ah3, blf[nt][0], blf[nt][1]);
                    mma_bf16(acc[mt][nt], al0, al1, al2, al3, bhf[nt][0], bhf[nt][1]);
                }
            }
        }
        __syncthreads();
    }

    // ---- epilogue: stores
    #pragma unroll
    for (int nt = 0; nt < 8; nt++) {
        int col = n0 + wn * 64 + nt * 8 + 2 * tq;
        float bv0 = bias[col], bv1 = bias[col + 1];
        #pragma unroll
        for (int mt = 0; mt < 2; mt++) {
            int r0 = m0 + wm * 32 + mt * 16 + g;
            float* d = acc[mt][nt];
            if (mode == 1) {
                if (r0 < M) {
                    float a = fmaxf(d[0] + bv0, 0.f), b = fmaxf(d[1] + bv1, 0.f);
                    uint32_t lo, hi = split_pack(a, b, lo);
                    size_t o = (size_t)r0 * Nout + col;
                    *(uint32_t*)(outh + o) = hi;
                    *(uint32_t*)(outl + o) = lo;
                }
                if (r0 + 8 < M) {
                    float a = fmaxf(d[2] + bv0, 0.f), b = fmaxf(d[3] + bv1, 0.f);
                    uint32_t lo, hi = split_pack(a, b, lo);
                    size_t o = (size_t)(r0 + 8) * Nout + col;
                    *(uint32_t*)(outh + o) = hi;
                    *(uint32_t*)(outl + o) = lo;
                }
            } else {
                if (r0 < M)
                    *(float2*)(outf + (size_t)r0 * 128 + col) =
                        make_float2(d[0] + bv0, d[1] + bv1);
                if (r0 + 8 < M)
                    *(float2*)(outf + (size_t)(r0 + 8) * 128 + col) =
                        make_float2(d[2] + bv0, d[3] + bv1);
            }
        }
    }

    // ---- fused column stats (mode 2): sum & sumsq over valid rows
    if (mode == 2) {
        float* ssum = (float*)smem;          // 128
        float* ssq  = (float*)smem + 128;    // 128
        if (tid < 128) { ssum[tid] = 0.f; ssq[tid] = 0.f; }
        __syncthreads();
        #pragma unroll
        for (int nt = 0; nt < 8; nt++) {
            int lcol = wn * 64 + nt * 8 + 2 * tq;
            float bv0 = bias[n0 + lcol], bv1 = bias[n0 + lcol + 1];
            float s0 = 0.f, s1 = 0.f, q0 = 0.f, q1 = 0.f;
            #pragma unroll
            for (int mt = 0; mt < 2; mt++) {
                int r0 = m0 + wm * 32 + mt * 16 + g;
                float* d = acc[mt][nt];
                if (r0 < M) {
                    float a = d[0] + bv0, b = d[1] + bv1;
                    s0 += a; q0 += a * a; s1 += b; q1 += b * b;
                }
                if (r0 + 8 < M) {
                    float a = d[2] + bv0, b = d[3] + bv1;
                    s0 += a; q0 += a * a; s1 += b; q1 += b * b;
                }
            }
            #pragma unroll
            for (int off = 4; off < 32; off <<= 1) {
                s0 += __shfl_xor_sync(0xFFFFFFFFu, s0, off);
                s1 += __shfl_xor_sync(0xFFFFFFFFu, s1, off);
                q0 += __shfl_xor_sync(0xFFFFFFFFu, q0, off);
                q1 += __shfl_xor_sync(0xFFFFFFFFu, q1, off);
            }
            if (lane < 4) {
                atomicAdd(&ssum[lcol], s0);
                atomicAdd(&ssum[lcol + 1], s1);
                atomicAdd(&ssq[lcol], q0);
                atomicAdd(&ssq[lcol + 1], q1);
            }
        }
        __syncthreads();
        if (tid < 128) {
            atomicAdd(&g_stats[tid], ssum[tid]);
            atomicAdd(&g_stats[128 + tid], ssq[tid]);
        }
    }
}

// final BatchNorm (no ReLU) -> d_out
__global__ void bn_kernel(const float* __restrict__ h2,
                          const float* __restrict__ gamma,
                          const float* __restrict__ beta,
                          float* __restrict__ out) {
    __shared__ float sc[128], sh[128];
    int tid = threadIdx.x;
    if (tid < 128) {
        float mu  = g_stats[tid] * (1.0f / NN);
        float var = g_stats[128 + tid] * (1.0f / NN) - mu * mu;
        float s = gamma[tid] * rsqrtf(var + BN_EPS);
        sc[tid] = s;
        sh[tid] = beta[tid] - mu * s;
    }
    __syncthreads();
    int idx = blockIdx.x * blockDim.x + tid;
    if (idx >= NN * 32) return;
    int c = (idx & 31) * 4;
    float4 v = ((const float4*)h2)[idx];
    float4 o;
    o.x = v.x * sc[c + 0] + sh[c + 0];
    o.y = v.y * sc[c + 1] + sh[c + 1];
    o.z = v.z * sc[c + 2] + sh[c + 2];
    o.w = v.w * sc[c + 3] + sh[c + 3];
    ((float4*)out)[idx] = o;
}

// ------------------------- host launcher -------------------------------------
extern "C" void kernel_launch(void* const* d_in, const int* in_sizes, int n_in,
                              void* d_out, int out_size) {
    const int*   x          = (const int*)d_in[0];
    const int*   edge_index = (const int*)d_in[1];
    const int*   edge_attr  = (const int*)d_in[2];
    const float* atom       = (const float*)d_in[3];
    const float* chir       = (const float*)d_in[4];
    const float* hyb        = (const float*)d_in[5];
    const float* e1         = (const float*)d_in[6];
    const float* e2         = (const float*)d_in[7];
    const float* W1         = (const float*)d_in[8];
    const float* b1         = (const float*)d_in[9];
    const float* W2         = (const float*)d_in[10];
    const float* b2         = (const float*)d_in[11];
    const float* gamma      = (const float*)d_in[12];
    const float* beta       = (const float*)d_in[13];
    float* out = (float*)d_out;

    const int* src = edge_index;
    const int* dst = edge_index + NE;

    float *p_h, *p_h2;
    __nv_bfloat16 *p_aggh, *p_aggl, *p_midh, *p_midl;
    __nv_bfloat16 *p_w1th, *p_w1tl, *p_w2th, *p_w2tl;
    cudaGetSymbolAddress((void**)&p_h, g_h);
    cudaGetSymbolAddress((void**)&p_h2, g_h2);
    cudaGetSymbolAddress((void**)&p_aggh, g_aggh);
    cudaGetSymbolAddress((void**)&p_aggl, g_aggl);
    cudaGetSymbolAddress((void**)&p_midh, g_midh);
    cudaGetSymbolAddress((void**)&p_midl, g_midl);
    cudaGetSymbolAddress((void**)&p_w1th, g_w1th);
    cudaGetSymbolAddress((void**)&p_w1tl, g_w1tl);
    cudaGetSymbolAddress((void**)&p_w2th, g_w2th);
    cudaGetSymbolAddress((void**)&p_w2tl, g_w2tl);

    cudaFuncSetAttribute(mma_gemm_kernel,
                         cudaFuncAttributeMaxDynamicSharedMemorySize, SMEM_MMA);

    // preprocessing: CSR-sort edges by destination
    zero_deg_kernel<<<(NN + 255) / 256, 256>>>();
    hist_kernel<<<(NE + 255) / 256, 256>>>(dst);
    scanA_kernel<<<NBLK_SCAN, 1024>>>();
    scanB_kernel<<<1, 64>>>();
    scanC_kernel<<<(NN + 255) / 256, 256>>>();
    scatter_kernel<<<(NE + 255) / 256, 256>>>(src, dst, edge_attr);

    init_h_kernel<<<(NN * 32 + 255) / 256, 256>>>(x, atom, chir, hyb);
    wconv_kernel<<<(NLAYER * 256 * 128 + 255) / 256, 256>>>(W1, W2);

    const int mb = (NN + 127) / 128;   // 391
    for (int l = 0; l < NLAYER; l++) {
        // edge table + BN affine of previous layer
        const float* gp = (l > 0) ? gamma + (l - 1) * 128 : gamma;
        const float* bp = (l > 0) ? beta + (l - 1) * 128 : beta;
        comb_kernel<<<1, 256>>>(e1, e2, gp, bp, l);
        // aggregate with fused BN(prev)+ReLU for l>0
        aggregate_kernel<<<(NN + 7) / 8, 256>>>(l == 0 ? p_h : p_h2, l > 0);
        // GEMM1: agg @ W1^T -> relu -> mid (bf16 split); zeroes g_stats
        mma_gemm_kernel<<<dim3(mb, 2), 256, SMEM_MMA>>>(
            p_aggh, p_aggl,
            p_w1th + (size_t)l * 256 * 128, p_w1tl + (size_t)l * 256 * 128,
            b1 + l * 256, NN, 128, 256, 1, p_midh, p_midl, nullptr);
        // GEMM2: mid @ W2^T -> h2 (fp32) + fused column stats
        mma_gemm_kernel<<<dim3(mb, 1), 256, SMEM_MMA>>>(
            p_midh, p_midl,
            p_w2th + (size_t)l * 128 * 256, p_w2tl + (size_t)l * 128 * 256,
            b2 + l * 128, NN, 256, 128, 2, nullptr, nullptr, p_h2);
    }
    // final BN (no ReLU) -> output
    bn_kernel<<<(NN * 32 + 255) / 256, 256>>>(
        p_h2, gamma + 4 * 128, beta + 4 * 128, out);
}